// round 6
// baseline (speedup 1.0000x reference)
#include <cuda_runtime.h>
#include <cuda_bf16.h>
#include <math.h>

// GAT layer, B=8, N=2048, F=64, ALPHA=0.2
// out = elu( softmax_j( lrelu(s_src[i]+s_dst[j]) ) @ Wh )
//
// exp(lrelu(s+d)) = (d > -s) ? exp(s)*exp(d) : exp(.2s)*exp(.2d)
// => sort by d, prefix sums of E1*Wh and E2*Wh, binary search per row.

#define NB 8
#define NN 2048
#define NF 64
#define NNODES (NB*NN)          // 16384
#define NR1 (NN+1)              // 2049

// ---- device scratch (static globals: no allocation allowed) ----
__device__ float g_Wh [NNODES*NF];     // Wh rows, original order
__device__ float g_Whs[NNODES*NF];     // Wh rows, sorted (by d) order
__device__ float g_s  [NNODES];        // s_src
__device__ float g_F1 [NNODES];        // exp(s_src)
__device__ float g_F2 [NNODES];        // exp(.2*s_src)
__device__ float g_d  [NNODES];        // s_dst
__device__ float g_E1 [NNODES];        // exp(s_dst)
__device__ float g_E2 [NNODES];        // exp(.2*s_dst)
__device__ float g_dsort[NNODES];      // sorted d per batch
__device__ int   g_perm [NNODES];      // permutation per batch (local idx)
__device__ float g_E1s[NNODES];        // E1 in sorted order
__device__ float g_E2s[NNODES];
__device__ float g_C1p[NB*NR1];        // exclusive prefix of E1s  (scalar)
__device__ float g_C2p[NB*NR1];        // exclusive prefix of E2s
__device__ float g_P1 [NB*NR1*NF];     // exclusive prefix of E1s*Whs, [b][r][o]
__device__ float g_P2 [NB*NR1*NF];
__device__ float g_seg1[NB*16*NF];     // segment sums (16 segs of 128 rows)
__device__ float g_seg2[NB*16*NF];

// ============================================================
// K1: Wh = h @ W ; s_src = Wh·a[:64] ; s_dst = Wh·a[64:]
// block 256 = 16 nodes x 16 lanes x 4 outputs; grid 1024
// ============================================================
__global__ void __launch_bounds__(256) k1_gemm(
    const float* __restrict__ h, const float* __restrict__ W,
    const float* __restrict__ a)
{
    __shared__ float sW[64*64];
    __shared__ float sh[16][64];
    __shared__ float sa[128];
    int tid = threadIdx.x;
    #pragma unroll
    for (int i = tid; i < 4096; i += 256) sW[i] = W[i];
    if (tid < 128) sa[tid] = a[tid];

    int g = tid >> 4, l = tid & 15;
    int node = blockIdx.x * 16 + g;
    int o = l * 4;
    float4 hv = *(const float4*)(h + node*64 + o);
    *(float4*)(&sh[g][o]) = hv;
    __syncthreads();

    float ax=0.f, ay=0.f, az=0.f, aw=0.f;
    #pragma unroll
    for (int f = 0; f < 64; f++) {
        float hf = sh[g][f];
        float4 w4 = *(const float4*)(&sW[f*64 + o]);
        ax += hf*w4.x; ay += hf*w4.y; az += hf*w4.z; aw += hf*w4.w;
    }
    float4 ov; ov.x=ax; ov.y=ay; ov.z=az; ov.w=aw;
    *(float4*)(&g_Wh[node*64 + o]) = ov;

    float ps = ax*sa[o]    + ay*sa[o+1]    + az*sa[o+2]    + aw*sa[o+3];
    float pd = ax*sa[64+o] + ay*sa[64+o+1] + az*sa[64+o+2] + aw*sa[64+o+3];
    #pragma unroll
    for (int d2 = 8; d2 >= 1; d2 >>= 1) {
        ps += __shfl_xor_sync(0xffffffffu, ps, d2);
        pd += __shfl_xor_sync(0xffffffffu, pd, d2);
    }
    if (l == 0) {
        g_s [node] = ps;
        g_F1[node] = expf(ps);
        g_F2[node] = expf(0.2f*ps);
        g_d [node] = pd;
        g_E1[node] = expf(pd);
        g_E2[node] = expf(0.2f*pd);
    }
}

// ============================================================
// K2: per-batch bitonic sort of (d, j) + gather E1/E2 + scalar scans
// block 1024, grid 8
// ============================================================
__device__ __forceinline__ void block_scan_2048(
    const float* sc, float* gout, float* wsum)
{
    int t = threadIdx.x, lane = t & 31, w = t >> 5;
    float x0 = sc[2*t], x1 = sc[2*t+1];
    float v = x0 + x1;
    float s = v;
    #pragma unroll
    for (int d2 = 1; d2 < 32; d2 <<= 1) {
        float nn = __shfl_up_sync(0xffffffffu, s, d2);
        if (lane >= d2) s += nn;
    }
    if (lane == 31) wsum[w] = s;
    __syncthreads();
    if (t < 32) {
        float ws = wsum[t]; float ss = ws;
        #pragma unroll
        for (int d2 = 1; d2 < 32; d2 <<= 1) {
            float nn = __shfl_up_sync(0xffffffffu, ss, d2);
            if (t >= d2) ss += nn;
        }
        wsum[t] = ss - ws;   // exclusive warp offset
    }
    __syncthreads();
    float incl = wsum[w] + s;       // inclusive over pairs [0..t]
    float excl = incl - v;          // exclusive before element 2t
    gout[2*t]   = excl;
    gout[2*t+1] = excl + x0;
    if (t == 1023) gout[2048] = incl;
}

__global__ void __launch_bounds__(1024) k2_sort(void)
{
    __shared__ float sk[2048];
    __shared__ int   sv[2048];
    __shared__ float sc[2048];
    __shared__ float wsum[32];
    int b = blockIdx.x, t = threadIdx.x;
    int base = b * NN;

    sk[t]      = g_d[base + t];      sv[t]      = t;
    sk[t+1024] = g_d[base + t+1024]; sv[t+1024] = t + 1024;
    __syncthreads();

    for (int k = 2; k <= 2048; k <<= 1) {
        for (int j = k >> 1; j > 0; j >>= 1) {
            #pragma unroll
            for (int e = 0; e < 2; e++) {
                int i = t + e*1024;
                int ixj = i ^ j;
                if (ixj > i) {
                    bool up = ((i & k) == 0);
                    float ki = sk[i], kj = sk[ixj];
                    if ((ki > kj) == up) {
                        sk[i] = kj; sk[ixj] = ki;
                        int vi = sv[i]; sv[i] = sv[ixj]; sv[ixj] = vi;
                    }
                }
            }
            __syncthreads();
        }
    }

    // write sorted keys/perm, gather E1 into sc
    #pragma unroll
    for (int e = 0; e < 2; e++) {
        int i = t + e*1024;
        int gi = base + i;
        g_dsort[gi] = sk[i];
        int p = sv[i];
        g_perm[gi] = p;
        float e1 = g_E1[base + p];
        g_E1s[gi] = e1;
        sc[i] = e1;
    }
    __syncthreads();
    block_scan_2048(sc, &g_C1p[b*NR1], wsum);
    __syncthreads();

    #pragma unroll
    for (int e = 0; e < 2; e++) {
        int i = t + e*1024;
        int p = sv[i];
        float e2 = g_E2[base + p];
        g_E2s[base + i] = e2;
        sc[i] = e2;
    }
    __syncthreads();
    block_scan_2048(sc, &g_C2p[b*NR1], wsum);
}

// ============================================================
// K2b: Whs[b][r][:] = Wh[b][perm[r]][:]   (row gather, coalesced)
// grid 4096, block 256
// ============================================================
__global__ void __launch_bounds__(256) k2b_gather(void)
{
    int idx = blockIdx.x * 256 + threadIdx.x;     // 0 .. NNODES*NF
    int rg  = idx >> 6;                            // global sorted row
    int o   = idx & 63;
    int b   = rg >> 11;
    int p   = g_perm[rg];
    g_Whs[idx] = g_Wh[((b << 11) + p) * 64 + o];
}

// ============================================================
// K3a: segment sums (16 segments of 128 rows per batch)
// grid 128 (b*16+seg), block 256 (o=tid&63, sub=tid>>6)
// ============================================================
__global__ void __launch_bounds__(256) k3a_segsum(void)
{
    int b = blockIdx.x >> 4, seg = blockIdx.x & 15;
    int o = threadIdx.x & 63, sub = threadIdx.x >> 6;
    int rbase = b*NN + seg*128 + sub*32;
    float a1 = 0.f, a2 = 0.f;
    #pragma unroll 4
    for (int rr = 0; rr < 32; rr++) {
        int r = rbase + rr;
        float w = g_Whs[r*64 + o];
        a1 += g_E1s[r] * w;
        a2 += g_E2s[r] * w;
    }
    __shared__ float r1[256], r2[256];
    r1[threadIdx.x] = a1; r2[threadIdx.x] = a2;
    __syncthreads();
    if (sub == 0) {
        float s1 = r1[o] + r1[64+o] + r1[128+o] + r1[192+o];
        float s2 = r2[o] + r2[64+o] + r2[128+o] + r2[192+o];
        int si = (b*16 + seg)*64 + o;
        g_seg1[si] = s1; g_seg2[si] = s2;
    }
}

// ============================================================
// K3b: in-segment sequential scan with segment carry
// grid 128 (b*16+seg), block 64 (o=tid)
// ============================================================
__global__ void __launch_bounds__(64) k3b_scan(void)
{
    int b = blockIdx.x >> 4, seg = blockIdx.x & 15;
    int o = threadIdx.x;
    float p1 = 0.f, p2 = 0.f;
    for (int s = 0; s < seg; s++) {
        p1 += g_seg1[(b*16 + s)*64 + o];
        p2 += g_seg2[(b*16 + s)*64 + o];
    }
    int rbase = b*NN + seg*128;
    int pbase = (b*NR1 + seg*128)*64 + o;
    #pragma unroll 8
    for (int rr = 0; rr < 128; rr++) {
        g_P1[pbase + rr*64] = p1;
        g_P2[pbase + rr*64] = p2;
        int r = rbase + rr;
        float w = g_Whs[r*64 + o];
        p1 += g_E1s[r] * w;
        p2 += g_E2s[r] * w;
    }
    if (seg == 15) {
        int pend = (b*NR1 + NN)*64 + o;
        g_P1[pend] = p1;
        g_P2[pend] = p2;
    }
}

// ============================================================
// K4: per-row binary search + combine + ELU
// grid 2048 (b = blk>>8, 8 nodes/block), block 256 (warp per node)
// ============================================================
__global__ void __launch_bounds__(256) k4_final(float* __restrict__ out)
{
    __shared__ float sd[2048];
    int b = blockIdx.x >> 8;
    int t = threadIdx.x;
    for (int i = t; i < 2048; i += 256) sd[i] = g_dsort[b*NN + i];
    __syncthreads();

    int warp = t >> 5, lane = t & 31;
    int il = (blockIdx.x & 255)*8 + warp;
    int n  = b*NN + il;

    float thr = -g_s[n];
    int lo = 0, hi = NN;
    while (lo < hi) {
        int mid = (lo + hi) >> 1;
        if (sd[mid] <= thr) lo = mid + 1; else hi = mid;
    }
    int k = lo;   // ranks >= k : d > -s  (branch exp(s)exp(d))

    float f1 = g_F1[n], f2 = g_F2[n];
    int cb = b*NR1;
    float denom = f1 * (g_C1p[cb + NN] - g_C1p[cb + k]) + f2 * g_C2p[cb + k];
    float inv = 1.0f / denom;

    int pk = (cb + k)  * 64;
    int pn = (cb + NN) * 64;
    #pragma unroll
    for (int hh = 0; hh < 2; hh++) {
        int o = lane + hh*32;
        float num = f1 * (g_P1[pn + o] - g_P1[pk + o]) + f2 * g_P2[pk + o];
        float hp = num * inv;
        out[n*64 + o] = hp > 0.f ? hp : expm1f(hp);
    }
}

// ============================================================
extern "C" void kernel_launch(void* const* d_in, const int* in_sizes, int n_in,
                              void* d_out, int out_size)
{
    const float* h = (const float*)d_in[0];   // (8,2048,64)
    const float* W = (const float*)d_in[1];   // (64,64)
    const float* a = (const float*)d_in[2];   // (128,1)
    float* out = (float*)d_out;               // (8,2048,64)

    k1_gemm  <<<NNODES/16, 256>>>(h, W, a);
    k2_sort  <<<NB, 1024>>>();
    k2b_gather<<<(NNODES*NF)/256, 256>>>();
    k3a_segsum<<<NB*16, 256>>>();
    k3b_scan <<<NB*16, 64>>>();
    k4_final <<<NB*256, 256>>>(out);
}

// round 7
// speedup vs baseline: 1.4923x; 1.4923x over previous
#include <cuda_runtime.h>
#include <cuda_bf16.h>
#include <math.h>

// GAT layer, B=8, N=2048, F=64, ALPHA=0.2
// exp(lrelu(s+d)) = (d > -s) ? exp(s)*exp(d) : exp(.2s)*exp(.2d)
// => sort by d, prefix sums of E*Wh, per-row rank -> O(N) softmax.

#define NB 8
#define NN 2048
#define NF 64
#define NNODES (NB*NN)          // 16384
#define NR1 (NN+1)              // 2049
#define SEGS 64                 // segments per batch
#define SROWS 32                // rows per segment

// ---- device scratch (no allocation allowed) ----
__device__ float  g_Wh  [NNODES*NF];   // Wh rows, original order
__device__ float  g_s   [NNODES];      // s_src
__device__ float2 g_F12 [NNODES];      // {exp(s), exp(.2s)}
__device__ float  g_d   [NNODES];      // s_dst
__device__ float2 g_E12 [NNODES];      // {exp(d), exp(.2d)} original order
__device__ float2 g_E12s[NNODES];      // sorted order
__device__ int    g_perm[NNODES];      // sorted-rank -> local node idx
__device__ int    g_k   [NNODES];      // per-node threshold rank
__device__ float  g_C1p [NB*NR1];      // exclusive prefix of E1s (scalar)
__device__ float  g_C2p [NB*NR1];
__device__ float2 g_P12 [NB*NR1*NF];   // exclusive prefix of {E1s,E2s}*Whs
__device__ float2 g_seg12[NB*SEGS*NF]; // per-segment sums

// ============================================================
// K1: Wh = h@W ; s_src/s_dst + exps.  64 nodes/block, grid 256.
// Layout: 16 lanes (o=4l) x 16 groups, 4 nodes per group.
// ============================================================
__global__ void __launch_bounds__(256) k1_gemm(
    const float* __restrict__ h, const float* __restrict__ W,
    const float* __restrict__ a)
{
    __shared__ float sW[64*64];
    __shared__ float sh[64][65];
    __shared__ float sa[128];
    int tid = threadIdx.x;
    #pragma unroll
    for (int i = tid; i < 4096; i += 256) sW[i] = W[i];
    if (tid < 128) sa[tid] = a[tid];

    int base = blockIdx.x * 64;
    for (int i = tid; i < 1024; i += 256) {     // 64 rows x 16 float4
        int row = i >> 4, c4 = i & 15;
        float4 v = *(const float4*)(h + (base + row)*64 + c4*4);
        sh[row][c4*4+0] = v.x; sh[row][c4*4+1] = v.y;
        sh[row][c4*4+2] = v.z; sh[row][c4*4+3] = v.w;
    }
    __syncthreads();

    int l = tid & 15, grp = tid >> 4;
    int o = l * 4;
    int nb = grp * 4;
    float acc[4][4] = {};
    #pragma unroll 8
    for (int f = 0; f < 64; f++) {
        float4 w4 = *(const float4*)(&sW[f*64 + o]);
        #pragma unroll
        for (int e = 0; e < 4; e++) {
            float hf = sh[nb + e][f];
            acc[e][0] += hf*w4.x; acc[e][1] += hf*w4.y;
            acc[e][2] += hf*w4.z; acc[e][3] += hf*w4.w;
        }
    }

    #pragma unroll
    for (int e = 0; e < 4; e++) {
        int node = base + nb + e;
        float4 ov; ov.x=acc[e][0]; ov.y=acc[e][1]; ov.z=acc[e][2]; ov.w=acc[e][3];
        *(float4*)(&g_Wh[node*64 + o]) = ov;
        float ps = acc[e][0]*sa[o]    + acc[e][1]*sa[o+1]
                 + acc[e][2]*sa[o+2]  + acc[e][3]*sa[o+3];
        float pd = acc[e][0]*sa[64+o] + acc[e][1]*sa[64+o+1]
                 + acc[e][2]*sa[64+o+2]+ acc[e][3]*sa[64+o+3];
        #pragma unroll
        for (int m = 8; m >= 1; m >>= 1) {
            ps += __shfl_xor_sync(0xffffffffu, ps, m);
            pd += __shfl_xor_sync(0xffffffffu, pd, m);
        }
        if (l == 0) {
            g_s[node] = ps;
            g_F12[node] = make_float2(expf(ps), expf(0.2f*ps));
            g_d[node] = pd;
            g_E12[node] = make_float2(expf(pd), expf(0.2f*pd));
        }
    }
}

// ============================================================
// K2: per-batch bitonic sort + rank search + scalar scans
// block 1024, grid 8
// ============================================================
__device__ __forceinline__ void block_scan_2048(
    const float* sc, float* gout, float* wsum)
{
    int t = threadIdx.x, lane = t & 31, w = t >> 5;
    float x0 = sc[2*t], x1 = sc[2*t+1];
    float v = x0 + x1;
    float s = v;
    #pragma unroll
    for (int d2 = 1; d2 < 32; d2 <<= 1) {
        float nn = __shfl_up_sync(0xffffffffu, s, d2);
        if (lane >= d2) s += nn;
    }
    if (lane == 31) wsum[w] = s;
    __syncthreads();
    if (t < 32) {
        float ws = wsum[t]; float ss = ws;
        #pragma unroll
        for (int d2 = 1; d2 < 32; d2 <<= 1) {
            float nn = __shfl_up_sync(0xffffffffu, ss, d2);
            if (t >= d2) ss += nn;
        }
        wsum[t] = ss - ws;
    }
    __syncthreads();
    float incl = wsum[w] + s;
    float excl = incl - v;
    gout[2*t]   = excl;
    gout[2*t+1] = excl + x0;
    if (t == 1023) gout[2048] = incl;
}

__global__ void __launch_bounds__(1024) k2_sort(void)
{
    __shared__ float sk[2048];
    __shared__ int   sv[2048];
    __shared__ float wsum[32];
    int b = blockIdx.x, t = threadIdx.x;
    int base = b * NN;

    sk[t]      = g_d[base + t];      sv[t]      = t;
    sk[t+1024] = g_d[base + t+1024]; sv[t+1024] = t + 1024;
    __syncthreads();

    for (int k = 2; k <= 2048; k <<= 1) {
        for (int j = k >> 1; j > 0; j >>= 1) {
            #pragma unroll
            for (int e = 0; e < 2; e++) {
                int i = t + e*1024;
                int ixj = i ^ j;
                if (ixj > i) {
                    bool up = ((i & k) == 0);
                    float ki = sk[i], kj = sk[ixj];
                    if ((ki > kj) == up) {
                        sk[i] = kj; sk[ixj] = ki;
                        int vi = sv[i]; sv[i] = sv[ixj]; sv[ixj] = vi;
                    }
                }
            }
            if (j >= 32) __syncthreads(); else __syncwarp();
        }
        __syncthreads();
    }

    // write perm + gathered exps
    int p0 = sv[t], p1 = sv[t + 1024];
    g_perm[base + t]        = p0;
    g_perm[base + t + 1024] = p1;
    float2 ea = g_E12[base + p0];
    float2 eb = g_E12[base + p1];
    g_E12s[base + t]        = ea;
    g_E12s[base + t + 1024] = eb;

    // per-node rank search against sorted keys (sk stable from here on)
    #pragma unroll
    for (int e = 0; e < 2; e++) {
        int n = base + t + e*1024;
        float thr = -g_s[n];
        int lo = 0, hi = NN;
        while (lo < hi) {
            int mid = (lo + hi) >> 1;
            if (sk[mid] <= thr) lo = mid + 1; else hi = mid;
        }
        g_k[n] = lo;
    }

    // scalar prefix scans (reuse sv as float buffer)
    float* sc = (float*)sv;
    sc[t] = ea.x; sc[t+1024] = eb.x;
    __syncthreads();
    block_scan_2048(sc, &g_C1p[b*NR1], wsum);
    __syncthreads();
    sc[t] = ea.y; sc[t+1024] = eb.y;
    __syncthreads();
    block_scan_2048(sc, &g_C2p[b*NR1], wsum);
}

// ============================================================
// K3a: segment sums of E12s * Wh[perm] (64 segs x 32 rows / batch)
// grid NB*SEGS=512, block 256 (o=tid&63, sub=tid>>6: 4 subs x 8 rows)
// ============================================================
__global__ void __launch_bounds__(256) k3a_segsum(void)
{
    int blk = blockIdx.x;
    int b = blk >> 6, seg = blk & 63;
    int o = threadIdx.x & 63, sub = threadIdx.x >> 6;
    __shared__ int    sperm[SROWS];
    __shared__ float2 sE[SROWS];
    int rbase = b*NN + seg*SROWS;
    if (threadIdx.x < SROWS) {
        sperm[threadIdx.x] = g_perm[rbase + threadIdx.x];
        sE[threadIdx.x]    = g_E12s[rbase + threadIdx.x];
    }
    __syncthreads();

    float a1 = 0.f, a2 = 0.f;
    #pragma unroll
    for (int rr = 0; rr < 8; rr++) {
        int lr = sub*8 + rr;
        float w = g_Wh[(b*NN + sperm[lr])*64 + o];
        a1 += sE[lr].x * w;
        a2 += sE[lr].y * w;
    }
    __shared__ float r1[256], r2[256];
    r1[threadIdx.x] = a1; r2[threadIdx.x] = a2;
    __syncthreads();
    if (sub == 0) {
        float2 s12 = make_float2(r1[o]+r1[64+o]+r1[128+o]+r1[192+o],
                                 r2[o]+r2[64+o]+r2[128+o]+r2[192+o]);
        g_seg12[(b*SEGS + seg)*64 + o] = s12;
    }
}

// ============================================================
// K3b: in-segment scan with cross-segment carry
// grid NB*SEGS=512, block 64 (o=tid)
// ============================================================
__global__ void __launch_bounds__(64) k3b_scan(void)
{
    int blk = blockIdx.x;
    int b = blk >> 6, seg = blk & 63;
    int o = threadIdx.x;
    __shared__ int    sperm[SROWS];
    __shared__ float2 sE[SROWS];
    if (o < SROWS) {
        sperm[o] = g_perm[b*NN + seg*SROWS + o];
        sE[o]    = g_E12s[b*NN + seg*SROWS + o];
    }
    __syncthreads();

    float2 p = make_float2(0.f, 0.f);
    for (int s = 0; s < seg; s++) {
        float2 v = g_seg12[(b*SEGS + s)*64 + o];
        p.x += v.x; p.y += v.y;
    }
    int pbase = (b*NR1 + seg*SROWS)*64 + o;
    #pragma unroll 8
    for (int rr = 0; rr < SROWS; rr++) {
        g_P12[pbase + rr*64] = p;
        float w = g_Wh[(b*NN + sperm[rr])*64 + o];
        p.x += sE[rr].x * w;
        p.y += sE[rr].y * w;
    }
    if (seg == SEGS-1)
        g_P12[(b*NR1 + NN)*64 + o] = p;
}

// ============================================================
// K4: flat combine + ELU. grid 4096, block 256 (one thread per output)
// ============================================================
__global__ void __launch_bounds__(256) k4_final(float* __restrict__ out)
{
    int idx = blockIdx.x * 256 + threadIdx.x;   // node*64 + o
    int n = idx >> 6, o = idx & 63;
    int b = n >> 11;
    int k = g_k[n];
    float2 f = g_F12[n];
    int cb = b * NR1;

    float denom = f.x * (g_C1p[cb + NN] - g_C1p[cb + k]) + f.y * g_C2p[cb + k];
    float inv = 1.0f / denom;

    float2 Pk = g_P12[(cb + k )*64 + o];
    float2 Pn = g_P12[(cb + NN)*64 + o];
    float num = f.x * (Pn.x - Pk.x) + f.y * Pk.y;
    float hp = num * inv;
    out[idx] = hp > 0.f ? hp : expm1f(hp);
}

// ============================================================
extern "C" void kernel_launch(void* const* d_in, const int* in_sizes, int n_in,
                              void* d_out, int out_size)
{
    const float* h = (const float*)d_in[0];   // (8,2048,64)
    const float* W = (const float*)d_in[1];   // (64,64)
    const float* a = (const float*)d_in[2];   // (128,1)
    float* out = (float*)d_out;               // (8,2048,64)

    k1_gemm   <<<NNODES/64, 256>>>(h, W, a);
    k2_sort   <<<NB, 1024>>>();
    k3a_segsum<<<NB*SEGS, 256>>>();
    k3b_scan  <<<NB*SEGS, 64>>>();
    k4_final  <<<(NNODES*NF)/256, 256>>>(out);
}

// round 8
// speedup vs baseline: 1.6940x; 1.1352x over previous
#include <cuda_runtime.h>
#include <cuda_bf16.h>
#include <math.h>

// GAT layer, B=8, N=2048, F=64, ALPHA=0.2
// exp(lrelu(s+d)) = (d > -s) ? exp(s)*exp(d) : exp(.2s)*exp(.2d)
// => sort by d, prefix sums of E*Wh, per-row rank -> O(N) softmax.

#define NB 8
#define NN 2048
#define NF 64
#define NNODES (NB*NN)          // 16384
#define NR1 (NN+1)              // 2049
#define SEGS 64                 // segments per batch
#define SROWS 32                // rows per segment

// ---- device scratch (no allocation allowed) ----
__device__ float  g_Wh  [NNODES*NF];   // Wh rows, original order
__device__ float  g_s   [NNODES];      // s_src
__device__ float2 g_F12 [NNODES];      // {exp(s), exp(.2s)}
__device__ float  g_d   [NNODES];      // s_dst
__device__ float2 g_E12 [NNODES];      // {exp(d), exp(.2d)} original order
__device__ float2 g_E12s[NNODES];      // sorted order
__device__ int    g_perm[NNODES];      // sorted-rank -> local node idx
__device__ int    g_k   [NNODES];      // per-node threshold rank
__device__ float  g_C1p [NB*NR1];      // exclusive prefix of E1s (scalar)
__device__ float  g_C2p [NB*NR1];
__device__ float2 g_P12 [NB*NR1*NF];   // exclusive prefix of {E1s,E2s}*Whs
__device__ float2 g_seg12[NB*SEGS*NF]; // per-segment sums

// ============================================================
// K1: Wh = h@W ; s_src/s_dst + exps.  64 nodes/block, grid 256.
// ============================================================
__global__ void __launch_bounds__(256) k1_gemm(
    const float* __restrict__ h, const float* __restrict__ W,
    const float* __restrict__ a)
{
    __shared__ float sW[64*64];
    __shared__ float sh[64][65];
    __shared__ float sa[128];
    int tid = threadIdx.x;
    #pragma unroll
    for (int i = tid; i < 4096; i += 256) sW[i] = W[i];
    if (tid < 128) sa[tid] = a[tid];

    int base = blockIdx.x * 64;
    for (int i = tid; i < 1024; i += 256) {     // 64 rows x 16 float4
        int row = i >> 4, c4 = i & 15;
        float4 v = *(const float4*)(h + (base + row)*64 + c4*4);
        sh[row][c4*4+0] = v.x; sh[row][c4*4+1] = v.y;
        sh[row][c4*4+2] = v.z; sh[row][c4*4+3] = v.w;
    }
    __syncthreads();

    int l = tid & 15, grp = tid >> 4;
    int o = l * 4;
    int nb = grp * 4;
    float acc[4][4] = {};
    #pragma unroll 8
    for (int f = 0; f < 64; f++) {
        float4 w4 = *(const float4*)(&sW[f*64 + o]);
        #pragma unroll
        for (int e = 0; e < 4; e++) {
            float hf = sh[nb + e][f];
            acc[e][0] += hf*w4.x; acc[e][1] += hf*w4.y;
            acc[e][2] += hf*w4.z; acc[e][3] += hf*w4.w;
        }
    }

    #pragma unroll
    for (int e = 0; e < 4; e++) {
        int node = base + nb + e;
        float4 ov; ov.x=acc[e][0]; ov.y=acc[e][1]; ov.z=acc[e][2]; ov.w=acc[e][3];
        *(float4*)(&g_Wh[node*64 + o]) = ov;
        float ps = acc[e][0]*sa[o]    + acc[e][1]*sa[o+1]
                 + acc[e][2]*sa[o+2]  + acc[e][3]*sa[o+3];
        float pd = acc[e][0]*sa[64+o] + acc[e][1]*sa[64+o+1]
                 + acc[e][2]*sa[64+o+2]+ acc[e][3]*sa[64+o+3];
        #pragma unroll
        for (int m = 8; m >= 1; m >>= 1) {
            ps += __shfl_xor_sync(0xffffffffu, ps, m);
            pd += __shfl_xor_sync(0xffffffffu, pd, m);
        }
        if (l == 0) {
            g_s[node] = ps;
            g_F12[node] = make_float2(expf(ps), expf(0.2f*ps));
            g_d[node] = pd;
            g_E12[node] = make_float2(expf(pd), expf(0.2f*pd));
        }
    }
}

// ============================================================
// K2: per-batch bitonic sort (packed u64) + rank search + scalar scans
// block 1024, grid 8
// ============================================================
__device__ __forceinline__ unsigned int f2key(float f) {
    unsigned int b = __float_as_uint(f);
    unsigned int m = (unsigned int)(-(int)(b >> 31)) | 0x80000000u;
    return b ^ m;
}

__device__ __forceinline__ void block_scan_2048(
    const float* sc, float* gout, float* wsum)
{
    int t = threadIdx.x, lane = t & 31, w = t >> 5;
    float x0 = sc[2*t], x1 = sc[2*t+1];
    float v = x0 + x1;
    float s = v;
    #pragma unroll
    for (int d2 = 1; d2 < 32; d2 <<= 1) {
        float nn = __shfl_up_sync(0xffffffffu, s, d2);
        if (lane >= d2) s += nn;
    }
    if (lane == 31) wsum[w] = s;
    __syncthreads();
    if (t < 32) {
        float ws = wsum[t]; float ss = ws;
        #pragma unroll
        for (int d2 = 1; d2 < 32; d2 <<= 1) {
            float nn = __shfl_up_sync(0xffffffffu, ss, d2);
            if (t >= d2) ss += nn;
        }
        wsum[t] = ss - ws;
    }
    __syncthreads();
    float incl = wsum[w] + s;
    float excl = incl - v;
    gout[2*t]   = excl;
    gout[2*t+1] = excl + x0;
    if (t == 1023) gout[2048] = incl;
}

__global__ void __launch_bounds__(1024) k2_sort(void)
{
    __shared__ unsigned long long skv[2048];
    __shared__ float wsum[32];
    int b = blockIdx.x, t = threadIdx.x;
    int base = b * NN;

    {
        unsigned int k0 = f2key(g_d[base + t]);
        unsigned int k1 = f2key(g_d[base + t + 1024]);
        skv[t]      = ((unsigned long long)k0 << 32) | (unsigned int)t;
        skv[t+1024] = ((unsigned long long)k1 << 32) | (unsigned int)(t + 1024);
    }
    __syncthreads();

    for (int k = 2; k <= 2048; k <<= 1) {
        for (int j = k >> 1; j > 0; j >>= 1) {
            #pragma unroll
            for (int e = 0; e < 2; e++) {
                int i = t + e*1024;
                int ixj = i ^ j;
                if (ixj > i) {
                    bool up = ((i & k) == 0);
                    unsigned long long vi = skv[i], vj = skv[ixj];
                    if ((vi > vj) == up) {
                        skv[i] = vj; skv[ixj] = vi;
                    }
                }
            }
            if (j >= 32) __syncthreads(); else __syncwarp();
        }
        __syncthreads();
    }

    // write perm + gathered exps
    int p0 = (int)(unsigned int)skv[t];
    int p1 = (int)(unsigned int)skv[t + 1024];
    g_perm[base + t]        = p0;
    g_perm[base + t + 1024] = p1;
    float2 ea = g_E12[base + p0];
    float2 eb = g_E12[base + p1];
    g_E12s[base + t]        = ea;
    g_E12s[base + t + 1024] = eb;

    // per-node rank search in sortable-uint key space
    #pragma unroll
    for (int e = 0; e < 2; e++) {
        int n = base + t + e*1024;
        unsigned int thrk = f2key(-g_s[n]);
        int lo = 0, hi = NN;
        while (lo < hi) {
            int mid = (lo + hi) >> 1;
            if ((unsigned int)(skv[mid] >> 32) <= thrk) lo = mid + 1; else hi = mid;
        }
        g_k[n] = lo;
    }
    __syncthreads();

    // scalar prefix scans (reuse skv memory as float buffer)
    float* sc = (float*)skv;
    sc[t] = ea.x; sc[t+1024] = eb.x;
    __syncthreads();
    block_scan_2048(sc, &g_C1p[b*NR1], wsum);
    __syncthreads();
    sc[t] = ea.y; sc[t+1024] = eb.y;
    __syncthreads();
    block_scan_2048(sc, &g_C2p[b*NR1], wsum);
}

// ============================================================
// K3a: segment sums of E12s * Wh[perm] (64 segs x 32 rows / batch)
// grid NB*SEGS=512, block 256 (o=tid&63, sub=tid>>6: 4 subs x 8 rows)
// ============================================================
__global__ void __launch_bounds__(256) k3a_segsum(void)
{
    int blk = blockIdx.x;
    int b = blk >> 6, seg = blk & 63;
    int o = threadIdx.x & 63, sub = threadIdx.x >> 6;
    __shared__ int    sperm[SROWS];
    __shared__ float2 sE[SROWS];
    int rbase = b*NN + seg*SROWS;
    if (threadIdx.x < SROWS) {
        sperm[threadIdx.x] = g_perm[rbase + threadIdx.x];
        sE[threadIdx.x]    = g_E12s[rbase + threadIdx.x];
    }
    __syncthreads();

    float a1 = 0.f, a2 = 0.f;
    #pragma unroll
    for (int rr = 0; rr < 8; rr++) {
        int lr = sub*8 + rr;
        float w = g_Wh[(b*NN + sperm[lr])*64 + o];
        a1 += sE[lr].x * w;
        a2 += sE[lr].y * w;
    }
    __shared__ float r1[256], r2[256];
    r1[threadIdx.x] = a1; r2[threadIdx.x] = a2;
    __syncthreads();
    if (sub == 0) {
        float2 s12 = make_float2(r1[o]+r1[64+o]+r1[128+o]+r1[192+o],
                                 r2[o]+r2[64+o]+r2[128+o]+r2[192+o]);
        g_seg12[(b*SEGS + seg)*64 + o] = s12;
    }
}

// ============================================================
// K3b: in-segment scan, 4 subs x 8 rows, parallel carry,
// single gather pass (Wh cached in registers).
// grid NB*SEGS=512, block 256
// ============================================================
__global__ void __launch_bounds__(256) k3b_scan(void)
{
    int blk = blockIdx.x;
    int b = blk >> 6, seg = blk & 63;
    int o = threadIdx.x & 63, sub = threadIdx.x >> 6;

    __shared__ int    sperm[SROWS];
    __shared__ float2 sE[SROWS];
    if (threadIdx.x < SROWS) {
        sperm[threadIdx.x] = g_perm[b*NN + seg*SROWS + threadIdx.x];
        sE[threadIdx.x]    = g_E12s[b*NN + seg*SROWS + threadIdx.x];
    }
    __syncthreads();

    // parallel carry: sub s takes segments s, s+4, s+8, ... < seg
    float2 carry = make_float2(0.f, 0.f);
    for (int s = sub; s < seg; s += 4) {
        float2 v = g_seg12[(b*SEGS + s)*64 + o];
        carry.x += v.x; carry.y += v.y;
    }

    // sub-chunk partial sum; cache gathered Wh in registers
    float w[8];
    float2 e[8];
    float2 loc = make_float2(0.f, 0.f);
    #pragma unroll
    for (int rr = 0; rr < 8; rr++) {
        int lr = sub*8 + rr;
        w[rr] = g_Wh[(b*NN + sperm[lr])*64 + o];
        e[rr] = sE[lr];
        loc.x += e[rr].x * w[rr];
        loc.y += e[rr].y * w[rr];
    }

    // combine across subs
    __shared__ float2 scar[4][64];
    __shared__ float2 sloc[4][64];
    scar[sub][o] = carry;
    sloc[sub][o] = loc;
    __syncthreads();

    float2 p = make_float2(0.f, 0.f);
    #pragma unroll
    for (int s2 = 0; s2 < 4; s2++) {
        float2 c = scar[s2][o];
        p.x += c.x; p.y += c.y;
    }
    #pragma unroll
    for (int s2 = 0; s2 < 3; s2++) {
        if (s2 < sub) {
            float2 c = sloc[s2][o];
            p.x += c.x; p.y += c.y;
        }
    }

    // write exclusive prefixes for own 8 rows (register replay)
    int pbase = (b*NR1 + seg*SROWS + sub*8)*64 + o;
    #pragma unroll
    for (int rr = 0; rr < 8; rr++) {
        g_P12[pbase + rr*64] = p;
        p.x += e[rr].x * w[rr];
        p.y += e[rr].y * w[rr];
    }
    if (seg == SEGS-1 && sub == 3)
        g_P12[(b*NR1 + NN)*64 + o] = p;
}

// ============================================================
// K4: flat combine + ELU. grid 4096, block 256 (one thread per output)
// ============================================================
__global__ void __launch_bounds__(256) k4_final(float* __restrict__ out)
{
    int idx = blockIdx.x * 256 + threadIdx.x;   // node*64 + o
    int n = idx >> 6, o = idx & 63;
    int b = n >> 11;
    int k = g_k[n];
    float2 f = g_F12[n];
    int cb = b * NR1;

    float denom = f.x * (g_C1p[cb + NN] - g_C1p[cb + k]) + f.y * g_C2p[cb + k];
    float inv = 1.0f / denom;

    float2 Pk = g_P12[(cb + k )*64 + o];
    float2 Pn = g_P12[(cb + NN)*64 + o];
    float num = f.x * (Pn.x - Pk.x) + f.y * Pk.y;
    float hp = num * inv;
    out[idx] = hp > 0.f ? hp : expm1f(hp);
}

// ============================================================
extern "C" void kernel_launch(void* const* d_in, const int* in_sizes, int n_in,
                              void* d_out, int out_size)
{
    const float* h = (const float*)d_in[0];   // (8,2048,64)
    const float* W = (const float*)d_in[1];   // (64,64)
    const float* a = (const float*)d_in[2];   // (128,1)
    float* out = (float*)d_out;               // (8,2048,64)

    k1_gemm   <<<NNODES/64, 256>>>(h, W, a);
    k2_sort   <<<NB, 1024>>>();
    k3a_segsum<<<NB*SEGS, 256>>>();
    k3b_scan  <<<NB*SEGS, 256>>>();
    k4_final  <<<(NNODES*NF)/256, 256>>>(out);
}